// round 1
// baseline (speedup 1.0000x reference)
#include <cuda_runtime.h>
#include <cuda_bf16.h>
#include <cstdint>

#define B_   4
#define T_   512
#define D_   256
#define H_   8
#define BH_  32
#define MTOK 2048
#define N3_  6144
#define SCALE_ 0.0625f   // 1/sqrt(256)

// ---------------- scratch (static device globals; no runtime alloc) ----------------
__device__ __align__(256) __nv_bfloat16 g_xb [MTOK * D_];
__device__ __align__(256) __nv_bfloat16 g_wqvb[N3_ * D_];
__device__ __align__(256) __nv_bfloat16 g_fwb [D_ * D_];
__device__ __align__(256) float          g_q  [BH_ * T_ * D_];          // [b,h,tq,d] fp32
__device__ __align__(256) __nv_bfloat16 g_vfT[BH_ * D_ * T_];           // [b,h,d,tq]
__device__ __align__(256) __nv_bfloat16 g_vbT[BH_ * D_ * T_];           // [b,h,d,tk]
__device__ __align__(256) float          g_sc [(size_t)BH_ * T_ * T_];  // [slab][tq][tk]
__device__ __align__(256) float          g_scT[(size_t)BH_ * T_ * T_];  // [slab][tk][tq]
__device__ __align__(256) __nv_bfloat16 g_pa [(size_t)BH_ * T_ * T_];   // softmax(g_sc) rows
__device__ __align__(256) __nv_bfloat16 g_paT[(size_t)BH_ * T_ * T_];   // softmax(g_scT) rows
__device__ __align__(256) float          g_bb [BH_ * T_ * D_];          // [slab][tq][d]
__device__ __align__(256) float          g_bf [BH_ * T_ * D_];          // [slab][tk][d]
__device__ __align__(256) __nv_bfloat16 g_y1 [MTOK * D_];

// ---------------- fp32<->bf16 prep ----------------
__global__ void k_convert(const float* __restrict__ x,
                          const float* __restrict__ wqv,
                          const float* __restrict__ fw) {
    int i = blockIdx.x * 256 + threadIdx.x;       // grid covers N3_*D_ = 1572864
    if (i < N3_ * D_)  g_wqvb[i] = __float2bfloat16(wqv[i]);
    if (i < MTOK * D_) g_xb[i]   = __float2bfloat16(x[i]);
    if (i < D_ * D_)   g_fwb[i]  = __float2bfloat16(fw[i]);
}

// ---------------- bf16 mma core: 64x64 block tile, C = A(MxK) * B(NxK)^T ----------------
#define LDS_K 40   // padded smem K-stride (elements) -> conflict-free frag loads

__device__ __forceinline__ void mma16816(float* c, const uint32_t* a, const uint32_t* b) {
    asm volatile(
        "mma.sync.aligned.m16n8k16.row.col.f32.bf16.bf16.f32 "
        "{%0,%1,%2,%3}, {%4,%5,%6,%7}, {%8,%9}, {%0,%1,%2,%3};\n"
        : "+f"(c[0]), "+f"(c[1]), "+f"(c[2]), "+f"(c[3])
        : "r"(a[0]), "r"(a[1]), "r"(a[2]), "r"(a[3]), "r"(b[0]), "r"(b[1]));
}

// block: 256 threads = 8 warps as 2(M) x 4(N); warp tile 32x16
__device__ __forceinline__ void gemm_core(
    const __nv_bfloat16* __restrict__ A, int lda,
    const __nv_bfloat16* __restrict__ Bm, int ldb,
    int m0, int n0, int K,
    __nv_bfloat16* sA, __nv_bfloat16* sB,
    float acc[2][2][4])
{
    int tid  = threadIdx.x;
    int warp = tid >> 5, lane = tid & 31;
    int wm = warp >> 2, wn = warp & 3;
    int lr = tid >> 2;           // 0..63
    int lc = (tid & 3) * 8;      // 0,8,16,24

    #pragma unroll
    for (int i = 0; i < 2; i++)
        #pragma unroll
        for (int j = 0; j < 2; j++)
            #pragma unroll
            for (int r = 0; r < 4; r++) acc[i][j][r] = 0.f;

    for (int k0 = 0; k0 < K; k0 += 32) {
        *(uint4*)&sA[lr * LDS_K + lc] = *(const uint4*)&A[(size_t)(m0 + lr) * lda + k0 + lc];
        *(uint4*)&sB[lr * LDS_K + lc] = *(const uint4*)&Bm[(size_t)(n0 + lr) * ldb + k0 + lc];
        __syncthreads();
        #pragma unroll
        for (int ks = 0; ks < 2; ks++) {
            uint32_t af[2][4], bfr[2][2];
            int arow = wm * 32 + (lane >> 2);
            int acol = ks * 16 + (lane & 3) * 2;
            #pragma unroll
            for (int i = 0; i < 2; i++) {
                const __nv_bfloat16* p = &sA[(arow + i * 16) * LDS_K + acol];
                af[i][0] = *(const uint32_t*)(p);
                af[i][1] = *(const uint32_t*)(p + 8 * LDS_K);
                af[i][2] = *(const uint32_t*)(p + 8);
                af[i][3] = *(const uint32_t*)(p + 8 * LDS_K + 8);
            }
            int brow = wn * 16 + (lane >> 2);
            #pragma unroll
            for (int j = 0; j < 2; j++) {
                const __nv_bfloat16* p = &sB[(brow + j * 8) * LDS_K + acol];
                bfr[j][0] = *(const uint32_t*)(p);
                bfr[j][1] = *(const uint32_t*)(p + 8);
            }
            #pragma unroll
            for (int i = 0; i < 2; i++)
                #pragma unroll
                for (int j = 0; j < 2; j++)
                    mma16816(acc[i][j], af[i], bfr[j]);
        }
        __syncthreads();
    }
}

#define EPILOGUE_POS(i, j, r, rl, cl)                          \
    int rl = (warp >> 2) * 32 + (i) * 16 + (lane >> 2) + (((r) >> 1) * 8); \
    int cl = (warp & 3) * 16 + (j) * 8 + (lane & 3) * 2 + ((r) & 1);

// ---------------- v projection: [2048 x 6144] = xb @ wqvb^T, scatter to q/vfT/vbT ----------------
__global__ void k_vproj(const float* __restrict__ wqv_b) {
    __shared__ __align__(16) __nv_bfloat16 sA[64 * LDS_K];
    __shared__ __align__(16) __nv_bfloat16 sB[64 * LDS_K];
    int m0 = blockIdx.y * 64, n0 = blockIdx.x * 64;
    float acc[2][2][4];
    gemm_core(g_xb, D_, g_wqvb, D_, m0, n0, D_, sA, sB, acc);
    int tid = threadIdx.x, warp = tid >> 5, lane = tid & 31;
    #pragma unroll
    for (int i = 0; i < 2; i++)
        #pragma unroll
        for (int j = 0; j < 2; j++)
            #pragma unroll
            for (int r = 0; r < 4; r++) {
                EPILOGUE_POS(i, j, r, rl, cl);
                int m = m0 + rl, n = n0 + cl;
                float v = acc[i][j][r] + wqv_b[n];
                int b = m >> 9, t = m & 511;
                int h3 = n >> 8, d = n & 255;
                if (h3 < 8) {
                    g_q[(((size_t)(b * H_ + h3) * T_) + t) * D_ + d] = v;
                } else if (h3 < 16) {
                    g_vfT[(((size_t)(b * H_ + (h3 - 8)) * D_) + d) * T_ + t] = __float2bfloat16(v);
                } else {
                    g_vbT[(((size_t)(b * H_ + (h3 - 16)) * D_) + d) * T_ + t] = __float2bfloat16(v);
                }
            }
}

// ---------------- L1 scores: a[slab][tq][tk] = -scale * sum_d |q - x*wk| (+ transposed copy) ----------------
__global__ void k_scores(const float* __restrict__ x, const float* __restrict__ wk) {
    __shared__ __align__(16) float sq[32][68];   // [d_local][row]
    __shared__ __align__(16) float sk[32][68];
    int slab = blockIdx.z;
    int b = slab >> 3, h = slab & 7;
    int tq0 = blockIdx.y * 64, tk0 = blockIdx.x * 64;
    int tid = threadIdx.x;
    int ty = tid >> 4, tx = tid & 15;
    int lrow = tid >> 2;
    int lc = (tid & 3) * 8;

    const float* qbase = g_q + ((size_t)slab * T_ + tq0) * D_;
    const float* xbase = x + ((size_t)b * T_ + tk0) * D_;
    const float* wkh = wk + h * D_;

    float acc[4][4];
    #pragma unroll
    for (int i = 0; i < 4; i++)
        #pragma unroll
        for (int j = 0; j < 4; j++) acc[i][j] = 0.f;

    for (int k0 = 0; k0 < D_; k0 += 32) {
        __syncthreads();
        float4 q0 = *(const float4*)&qbase[lrow * D_ + k0 + lc];
        float4 q1 = *(const float4*)&qbase[lrow * D_ + k0 + lc + 4];
        float4 x0 = *(const float4*)&xbase[lrow * D_ + k0 + lc];
        float4 x1 = *(const float4*)&xbase[lrow * D_ + k0 + lc + 4];
        float4 w0 = *(const float4*)&wkh[k0 + lc];
        float4 w1 = *(const float4*)&wkh[k0 + lc + 4];
        sq[lc + 0][lrow] = q0.x; sq[lc + 1][lrow] = q0.y;
        sq[lc + 2][lrow] = q0.z; sq[lc + 3][lrow] = q0.w;
        sq[lc + 4][lrow] = q1.x; sq[lc + 5][lrow] = q1.y;
        sq[lc + 6][lrow] = q1.z; sq[lc + 7][lrow] = q1.w;
        sk[lc + 0][lrow] = x0.x * w0.x; sk[lc + 1][lrow] = x0.y * w0.y;
        sk[lc + 2][lrow] = x0.z * w0.z; sk[lc + 3][lrow] = x0.w * w0.w;
        sk[lc + 4][lrow] = x1.x * w1.x; sk[lc + 5][lrow] = x1.y * w1.y;
        sk[lc + 6][lrow] = x1.z * w1.z; sk[lc + 7][lrow] = x1.w * w1.w;
        __syncthreads();
        #pragma unroll
        for (int c = 0; c < 32; c++) {
            float4 qv = *(const float4*)&sq[c][ty * 4];
            float4 kv = *(const float4*)&sk[c][tx * 4];
            acc[0][0] += fabsf(qv.x - kv.x); acc[0][1] += fabsf(qv.x - kv.y);
            acc[0][2] += fabsf(qv.x - kv.z); acc[0][3] += fabsf(qv.x - kv.w);
            acc[1][0] += fabsf(qv.y - kv.x); acc[1][1] += fabsf(qv.y - kv.y);
            acc[1][2] += fabsf(qv.y - kv.z); acc[1][3] += fabsf(qv.y - kv.w);
            acc[2][0] += fabsf(qv.z - kv.x); acc[2][1] += fabsf(qv.z - kv.y);
            acc[2][2] += fabsf(qv.z - kv.z); acc[2][3] += fabsf(qv.z - kv.w);
            acc[3][0] += fabsf(qv.w - kv.x); acc[3][1] += fabsf(qv.w - kv.y);
            acc[3][2] += fabsf(qv.w - kv.z); acc[3][3] += fabsf(qv.w - kv.w);
        }
    }

    size_t base = (size_t)slab * T_ * T_;
    #pragma unroll
    for (int i = 0; i < 4; i++) {
        float4 o = make_float4(-SCALE_ * acc[i][0], -SCALE_ * acc[i][1],
                               -SCALE_ * acc[i][2], -SCALE_ * acc[i][3]);
        *(float4*)&g_sc[base + (size_t)(tq0 + ty * 4 + i) * T_ + tk0 + tx * 4] = o;
    }
    #pragma unroll
    for (int j = 0; j < 4; j++) {
        float4 o = make_float4(-SCALE_ * acc[0][j], -SCALE_ * acc[1][j],
                               -SCALE_ * acc[2][j], -SCALE_ * acc[3][j]);
        *(float4*)&g_scT[base + (size_t)(tk0 + tx * 4 + j) * T_ + tq0 + ty * 4] = o;
    }
}

// ---------------- row softmax -> bf16 probs ----------------
__global__ void k_softmax(int which) {
    const float* S = which ? g_scT : g_sc;
    __nv_bfloat16* P = which ? g_paT : g_pa;
    int row = blockIdx.x, slab = blockIdx.y;
    const float* r = S + ((size_t)slab * T_ + row) * T_;
    int tid = threadIdx.x;                  // 128 threads
    float4 v = *(const float4*)&r[tid * 4];
    float m = fmaxf(fmaxf(v.x, v.y), fmaxf(v.z, v.w));
    #pragma unroll
    for (int o = 16; o; o >>= 1) m = fmaxf(m, __shfl_xor_sync(0xffffffffu, m, o));
    __shared__ float redm[4], reds[4];
    int warp = tid >> 5;
    if ((tid & 31) == 0) redm[warp] = m;
    __syncthreads();
    m = fmaxf(fmaxf(redm[0], redm[1]), fmaxf(redm[2], redm[3]));
    float e0 = __expf(v.x - m), e1 = __expf(v.y - m);
    float e2 = __expf(v.z - m), e3 = __expf(v.w - m);
    float s = (e0 + e1) + (e2 + e3);
    #pragma unroll
    for (int o = 16; o; o >>= 1) s += __shfl_xor_sync(0xffffffffu, s, o);
    if ((tid & 31) == 0) reds[warp] = s;
    __syncthreads();
    s = (reds[0] + reds[1]) + (reds[2] + reds[3]);
    float inv = 1.f / s;
    __nv_bfloat16* p = P + ((size_t)slab * T_ + row) * T_ + tid * 4;
    p[0] = __float2bfloat16(e0 * inv);
    p[1] = __float2bfloat16(e1 * inv);
    p[2] = __float2bfloat16(e2 * inv);
    p[3] = __float2bfloat16(e3 * inv);
}

// ---------------- AV GEMM per slab: C[t][d] = P(TxT) @ VT(DxT)^T ----------------
__global__ void k_av(int which) {
    const __nv_bfloat16* Pm = which ? g_paT : g_pa;
    const __nv_bfloat16* VT = which ? g_vfT : g_vbT;
    float* C = which ? g_bf : g_bb;
    __shared__ __align__(16) __nv_bfloat16 sA[64 * LDS_K];
    __shared__ __align__(16) __nv_bfloat16 sB[64 * LDS_K];
    int slab = blockIdx.z;
    int m0 = blockIdx.y * 64, n0 = blockIdx.x * 64;
    float acc[2][2][4];
    gemm_core(Pm + (size_t)slab * T_ * T_, T_,
              VT + (size_t)slab * D_ * T_, T_,
              m0, n0, T_, sA, sB, acc);
    int tid = threadIdx.x, warp = tid >> 5, lane = tid & 31;
    float* Cs = C + (size_t)slab * T_ * D_;
    #pragma unroll
    for (int i = 0; i < 2; i++)
        #pragma unroll
        for (int j = 0; j < 2; j++)
            #pragma unroll
            for (int r = 0; r < 4; r++) {
                EPILOGUE_POS(i, j, r, rl, cl);
                Cs[(size_t)(m0 + rl) * D_ + n0 + cl] = acc[i][j][r];
            }
}

// ---------------- head reduce + SiLU -> y1 (bf16) ----------------
__global__ void k_bo() {
    int idx = blockIdx.x * 256 + threadIdx.x;   // 0 .. 524287
    int bt = idx >> 8;                          // token
    int d = idx & 255;
    int b = bt >> 9, t = bt & 511;
    float s = 0.f;
    #pragma unroll
    for (int h = 0; h < H_; h++) {
        size_t o = (((size_t)(b * H_ + h) * T_) + t) * D_ + d;
        s += g_bf[o] + g_bb[o];
    }
    float sig = 1.f / (1.f + __expf(-1.702f * s));
    g_y1[idx] = __float2bfloat16(s * sig);
}

// ---------------- final fanin GEMM + bias + residual ----------------
__global__ void k_final(const float* __restrict__ x,
                        const float* __restrict__ fb,
                        float* __restrict__ out) {
    __shared__ __align__(16) __nv_bfloat16 sA[64 * LDS_K];
    __shared__ __align__(16) __nv_bfloat16 sB[64 * LDS_K];
    int m0 = blockIdx.y * 64, n0 = blockIdx.x * 64;
    float acc[2][2][4];
    gemm_core(g_y1, D_, g_fwb, D_, m0, n0, D_, sA, sB, acc);
    int tid = threadIdx.x, warp = tid >> 5, lane = tid & 31;
    #pragma unroll
    for (int i = 0; i < 2; i++)
        #pragma unroll
        for (int j = 0; j < 2; j++)
            #pragma unroll
            for (int r = 0; r < 4; r++) {
                EPILOGUE_POS(i, j, r, rl, cl);
                int m = m0 + rl, n = n0 + cl;
                out[(size_t)m * D_ + n] = acc[i][j][r] + fb[n] + x[(size_t)m * D_ + n];
            }
}

// ---------------- launch ----------------
extern "C" void kernel_launch(void* const* d_in, const int* in_sizes, int n_in,
                              void* d_out, int out_size) {
    const float* x       = (const float*)d_in[0];
    const float* wk      = (const float*)d_in[1];
    const float* wqv_w   = (const float*)d_in[2];
    const float* wqv_b   = (const float*)d_in[3];
    const float* fanin_w = (const float*)d_in[4];
    const float* fanin_b = (const float*)d_in[5];
    float* out = (float*)d_out;

    k_convert<<<6144, 256>>>(x, wqv_w, fanin_w);
    k_vproj<<<dim3(96, 32), 256>>>(wqv_b);
    k_scores<<<dim3(8, 8, 32), 256>>>(x, wk);
    k_softmax<<<dim3(512, 32), 128>>>(0);
    k_softmax<<<dim3(512, 32), 128>>>(1);
    k_av<<<dim3(4, 8, 32), 256>>>(0);
    k_av<<<dim3(4, 8, 32), 256>>>(1);
    k_bo<<<2048, 256>>>();
    k_final<<<dim3(4, 32), 256>>>(x, fanin_b, out);
}